// round 8
// baseline (speedup 1.0000x reference)
#include <cuda_runtime.h>
#include <cuda_bf16.h>
#include <cstdint>

#define N_ROWS   4194304
#define DIM      64
#define NUM_SEG  131072

// ---------------- scratch (no allocations allowed) ----------------
__device__ float g_segsum[NUM_SEG];

// ---------------- kernel 0: init ----------------
__global__ void k_init() {
    int i = blockIdx.x * blockDim.x + threadIdx.x;   // NUM_SEG/4 threads
    reinterpret_cast<float4*>(g_segsum)[i] = make_float4(0.f, 0.f, 0.f, 0.f);
}

// ---------------- kernel 1: fused GEMV + exp + segment sum ----------------
// 16 lanes per row (one float4 each); a warp covers 512B contiguous per
// LDG.128 -> 4 lines/instr. ALL 16 loads are staged upfront (MLP=16/thread)
// so the shfl reduction + epilogue overlap load latency instead of gating
// the second load batch. Head lanes (0,16) own 16 consecutive rows each and
// run-length-merge atomicAdds into g_segsum (seg sorted).
// X streamed with __ldcs (evict-first) so out/seg stay L2-resident for k_norm.
__global__ void __launch_bounds__(256) k_main(
    const float* __restrict__ X,
    const int*   __restrict__ seg,
    const float* __restrict__ W,
    const float* __restrict__ b,
    float*       __restrict__ out)
{
    const int lane   = threadIdx.x & 31;
    const int col    = lane & 15;          // float4 index within row
    const int half   = lane >> 4;
    const int warpId = (blockIdx.x * blockDim.x + threadIdx.x) >> 5;
    const int rowBase = warpId * 32;       // 32 rows per warp
    const int myRow0  = rowBase + 16 * half;

    const float w0 = __ldg(&W[col * 4 + 0]);
    const float w1 = __ldg(&W[col * 4 + 1]);
    const float w2 = __ldg(&W[col * 4 + 2]);
    const float w3 = __ldg(&W[col * 4 + 3]);
    const float b0 = __ldg(&b[0]);

    const float4* __restrict__ Xv = reinterpret_cast<const float4*>(X);
    const size_t base = (size_t)myRow0 * (DIM / 4) + col;

    const bool isHead = (col == 0);

    // stage ALL 16 row-loads upfront — 16 outstanding LDG.128 per thread
    float4 xs[16];
#pragma unroll
    for (int u = 0; u < 16; ++u)
        xs[u] = __ldcs(&Xv[base + (size_t)u * (DIM / 4)]);

    // head lanes preload their 16 seg ids (overlaps with X loads in flight)
    int sid[16];
    if (isHead) {
        const int4* s4 = reinterpret_cast<const int4*>(seg + myRow0);
#pragma unroll
        for (int q = 0; q < 4; ++q) {
            int4 v = __ldg(&s4[q]);
            sid[4 * q + 0] = v.x; sid[4 * q + 1] = v.y;
            sid[4 * q + 2] = v.z; sid[4 * q + 3] = v.w;
        }
    }

    float accs[16];
#pragma unroll
    for (int u = 0; u < 16; ++u) {
        float a = xs[u].x * w0 + xs[u].y * w1 + xs[u].z * w2 + xs[u].w * w3;
#pragma unroll
        for (int d = 8; d >= 1; d >>= 1)
            a += __shfl_xor_sync(0xffffffffu, a, d);
        accs[u] = a;
    }

    if (isHead) {
        float e[16];
#pragma unroll
        for (int u = 0; u < 16; ++u)
            e[u] = __expf(accs[u] + b0);

        float4* ov = reinterpret_cast<float4*>(out + myRow0);
#pragma unroll
        for (int q = 0; q < 4; ++q)
            ov[q] = make_float4(e[4 * q], e[4 * q + 1], e[4 * q + 2], e[4 * q + 3]);

        // run-length-merged segment sums
        int   curSeg = sid[0];
        float curAcc = e[0];
#pragma unroll
        for (int u = 1; u < 16; ++u) {
            int s = sid[u];
            if (s != curSeg) {
                atomicAdd(&g_segsum[curSeg], curAcc);
                curSeg = s;
                curAcc = e[u];
            } else {
                curAcc += e[u];
            }
        }
        atomicAdd(&g_segsum[curSeg], curAcc);
    }
}

// ---------------- kernel 2: normalize (8 rows / thread) ----------------
__global__ void __launch_bounds__(256) k_norm(
    const int* __restrict__ seg,
    float*     __restrict__ out)
{
    int t = blockIdx.x * blockDim.x + threadIdx.x;   // rows 8t..8t+7

    const int4*   sv = reinterpret_cast<const int4*>(seg) + 2 * t;
    float4*       ov = reinterpret_cast<float4*>(out) + 2 * t;

    int4   sa = __ldg(&sv[0]);
    int4   sb = __ldg(&sv[1]);
    float4 va = ov[0];
    float4 vb = ov[1];

    int s[8] = { sa.x, sa.y, sa.z, sa.w, sb.x, sb.y, sb.z, sb.w };
    float v[8] = { va.x, va.y, va.z, va.w, vb.x, vb.y, vb.z, vb.w };

    int   cur = s[0];
    float inv = __frcp_rn(g_segsum[cur]);
#pragma unroll
    for (int u = 0; u < 8; ++u) {
        if (s[u] != cur) { cur = s[u]; inv = __frcp_rn(g_segsum[cur]); }
        v[u] *= inv;
    }

    ov[0] = make_float4(v[0], v[1], v[2], v[3]);
    ov[1] = make_float4(v[4], v[5], v[6], v[7]);
}

// ---------------- launch ----------------
extern "C" void kernel_launch(void* const* d_in, const int* in_sizes, int n_in,
                              void* d_out, int out_size)
{
    const float* X   = (const float*)d_in[0];
    const int*   seg = (const int*)  d_in[1];
    const float* W   = (const float*)d_in[2];
    const float* b   = (const float*)d_in[3];
    float* out = (float*)d_out;

    k_init<<<NUM_SEG / 4 / 256, 256>>>();
    k_main<<<N_ROWS / 256, 256>>>(X, seg, W, b, out);
    k_norm<<<N_ROWS / 8 / 256, 256>>>(seg, out);
}

// round 9
// speedup vs baseline: 1.1431x; 1.1431x over previous
#include <cuda_runtime.h>
#include <cuda_bf16.h>
#include <cstdint>

#define N_ROWS   4194304
#define DIM      64
#define NUM_SEG  131072

// ---------------- scratch (no allocations allowed) ----------------
__device__ float g_segsum[NUM_SEG];

// ---------------- kernel 0: init ----------------
__global__ void k_init() {
    int i = blockIdx.x * blockDim.x + threadIdx.x;   // NUM_SEG/4 threads
    reinterpret_cast<float4*>(g_segsum)[i] = make_float4(0.f, 0.f, 0.f, 0.f);
}

// ---------------- kernel 1: fused GEMV + exp + segment sum ----------------
// 16 lanes per row (one float4 each); a warp covers 512B contiguous per
// LDG.128 -> 4 lines/instr. Two batches of 8 staged loads: 8x LDG.128 per
// thread in flight keeps registers ~80 (3+ blocks/SM) — the R8 experiment
// showed 16-deep staging spills and regresses. Head lanes (0,16) own 16
// consecutive rows each and run-length-merge atomicAdds into g_segsum
// (seg sorted). X streamed with __ldcs (evict-first) so out/seg stay
// L2-resident for k_norm.
__global__ void __launch_bounds__(256) k_main(
    const float* __restrict__ X,
    const int*   __restrict__ seg,
    const float* __restrict__ W,
    const float* __restrict__ b,
    float*       __restrict__ out)
{
    const int lane   = threadIdx.x & 31;
    const int col    = lane & 15;          // float4 index within row
    const int half   = lane >> 4;
    const int warpId = (blockIdx.x * blockDim.x + threadIdx.x) >> 5;
    const int rowBase = warpId * 32;       // 32 rows per warp
    const int myRow0  = rowBase + 16 * half;

    const float w0 = __ldg(&W[col * 4 + 0]);
    const float w1 = __ldg(&W[col * 4 + 1]);
    const float w2 = __ldg(&W[col * 4 + 2]);
    const float w3 = __ldg(&W[col * 4 + 3]);
    const float b0 = __ldg(&b[0]);

    const float4* __restrict__ Xv = reinterpret_cast<const float4*>(X);
    const size_t base = (size_t)myRow0 * (DIM / 4) + col;

    const bool isHead = (col == 0);

    // head lanes preload their 16 seg ids (aligned int4 x4)
    int sid[16];
    if (isHead) {
        const int4* s4 = reinterpret_cast<const int4*>(seg + myRow0);
#pragma unroll
        for (int q = 0; q < 4; ++q) {
            int4 v = __ldg(&s4[q]);
            sid[4 * q + 0] = v.x; sid[4 * q + 1] = v.y;
            sid[4 * q + 2] = v.z; sid[4 * q + 3] = v.w;
        }
    }

    int   curSeg = -1;
    float curAcc = 0.0f;

#pragma unroll
    for (int ii = 0; ii < 16; ii += 8) {
        float4 xs[8];
#pragma unroll
        for (int u = 0; u < 8; ++u)
            xs[u] = __ldcs(&Xv[base + (size_t)(ii + u) * (DIM / 4)]);

        float accs[8];
#pragma unroll
        for (int u = 0; u < 8; ++u) {
            float a = xs[u].x * w0 + xs[u].y * w1 + xs[u].z * w2 + xs[u].w * w3;
#pragma unroll
            for (int d = 8; d >= 1; d >>= 1)
                a += __shfl_xor_sync(0xffffffffu, a, d);
            accs[u] = a;
        }

        if (isHead) {
            float e[8];
#pragma unroll
            for (int u = 0; u < 8; ++u)
                e[u] = __expf(accs[u] + b0);

            float4* ov = reinterpret_cast<float4*>(out + myRow0 + ii);
            ov[0] = make_float4(e[0], e[1], e[2], e[3]);
            ov[1] = make_float4(e[4], e[5], e[6], e[7]);

            // run-length-merged segment sums
#pragma unroll
            for (int u = 0; u < 8; ++u) {
                int s = sid[ii + u];
                if (s != curSeg) {
                    if (curSeg >= 0) atomicAdd(&g_segsum[curSeg], curAcc);
                    curSeg = s;
                    curAcc = e[u];
                } else {
                    curAcc += e[u];
                }
            }
        }
    }
    if (isHead && curSeg >= 0) atomicAdd(&g_segsum[curSeg], curAcc);
}

// ---------------- kernel 2: normalize (8 rows / thread) ----------------
__global__ void __launch_bounds__(256) k_norm(
    const int* __restrict__ seg,
    float*     __restrict__ out)
{
    int t = blockIdx.x * blockDim.x + threadIdx.x;   // rows 8t..8t+7

    const int4*   sv = reinterpret_cast<const int4*>(seg) + 2 * t;
    float4*       ov = reinterpret_cast<float4*>(out) + 2 * t;

    int4   sa = __ldg(&sv[0]);
    int4   sb = __ldg(&sv[1]);
    float4 va = ov[0];
    float4 vb = ov[1];

    int s[8] = { sa.x, sa.y, sa.z, sa.w, sb.x, sb.y, sb.z, sb.w };
    float v[8] = { va.x, va.y, va.z, va.w, vb.x, vb.y, vb.z, vb.w };

    int   cur = s[0];
    float inv = __frcp_rn(g_segsum[cur]);
#pragma unroll
    for (int u = 0; u < 8; ++u) {
        if (s[u] != cur) { cur = s[u]; inv = __frcp_rn(g_segsum[cur]); }
        v[u] *= inv;
    }

    ov[0] = make_float4(v[0], v[1], v[2], v[3]);
    ov[1] = make_float4(v[4], v[5], v[6], v[7]);
}

// ---------------- launch ----------------
extern "C" void kernel_launch(void* const* d_in, const int* in_sizes, int n_in,
                              void* d_out, int out_size)
{
    const float* X   = (const float*)d_in[0];
    const int*   seg = (const int*)  d_in[1];
    const float* W   = (const float*)d_in[2];
    const float* b   = (const float*)d_in[3];
    float* out = (float*)d_out;

    k_init<<<NUM_SEG / 4 / 256, 256>>>();
    k_main<<<N_ROWS / 256, 256>>>(X, seg, W, b, out);
    k_norm<<<N_ROWS / 8 / 256, 256>>>(seg, out);
}